// round 3
// baseline (speedup 1.0000x reference)
#include <cuda_runtime.h>
#include <math.h>
#include <stdint.h>

// Problem constants (fixed by reference: N=32, C=256, H=W=32)
#define NB 32
#define CDIM 256
#define HW 1024
#define WD 32

// ---------------- device scratch (no allocations allowed) ----------------
__device__ double g_sum[64];                 // masked cos sum per (loss, n)
__device__ double g_cnt[64];                 // mask count per (loss, n)
__device__ float  g_norms[4][NB * HW];       // ||.|| for p1,p2,z1,z2
__device__ float  g_cx[2][NB * HW];          // centers x for coord_1, coord_2
__device__ float  g_cy[2][NB * HW];          // centers y
__device__ float  g_maxdiag[NB];             // max(diag1, diag2) per n

// Round fp32 -> TF32 (10-bit mantissa), same conversion cuBLAS/CUTLASS use.
// This replicates the input quantization of the reference's TF32 einsum.
__device__ __forceinline__ float tf32r(float x) {
    uint32_t u;
    asm("cvt.rna.tf32.f32 %0, %1;" : "=r"(u) : "f"(x));
    return __uint_as_float(u);
}

// ---------------- kernels ----------------
__global__ void zero_kernel() {
    int i = threadIdx.x;
    if (i < 64) { g_sum[i] = 0.0; g_cnt[i] = 0.0; }
}

// grid (NB, 4), block 1024: tensor t, sample n, one thread per spatial p.
// Norms are NOT a matmul in the reference -> exact fp32 (no TF32 rounding).
__global__ void norms_kernel(const float* __restrict__ p1, const float* __restrict__ p2,
                             const float* __restrict__ z1, const float* __restrict__ z2) {
    int n = blockIdx.x;
    int t = blockIdx.y;
    int p = threadIdx.x;
    const float* src = (t == 0) ? p1 : (t == 1) ? p2 : (t == 2) ? z1 : z2;
    const float* base = src + (size_t)n * CDIM * HW + p;
    float acc = 0.f;
#pragma unroll 8
    for (int c = 0; c < CDIM; ++c) {
        float v = base[(size_t)c * HW];
        acc += v * v;
    }
    g_norms[t][n * HW + p] = sqrtf(acc);
}

// grid (NB), block 1024: centers for both coord sets + max_diag, matching
// the reference arithmetic exactly (fp32, same op order).
__global__ void centers_kernel(const float* __restrict__ c1, const float* __restrict__ c2) {
    int n = blockIdx.x;
    int p = threadIdx.x;
    float a0 = c1[n * 4 + 0], a1 = c1[n * 4 + 1], a2 = c1[n * 4 + 2], a3 = c1[n * 4 + 3];
    float b0 = c2[n * 4 + 0], b1 = c2[n * 4 + 1], b2 = c2[n * 4 + 2], b3 = c2[n * 4 + 3];
    float bw1 = __fdiv_rn(__fsub_rn(a2, a0), 32.0f), bh1 = __fdiv_rn(__fsub_rn(a3, a1), 32.0f);
    float bw2 = __fdiv_rn(__fsub_rn(b2, b0), 32.0f), bh2 = __fdiv_rn(__fsub_rn(b3, b1), 32.0f);
    float x = (float)(p % WD);
    float y = (float)(p / WD);
    // (x+0.5)*bw + sx with separate mul/add rounding (no FMA contraction),
    // matching XLA's elementwise mul-then-add.
    g_cx[0][n * HW + p] = __fadd_rn(__fmul_rn(__fadd_rn(x, 0.5f), bw1), a0);
    g_cy[0][n * HW + p] = __fadd_rn(__fmul_rn(__fadd_rn(y, 0.5f), bh1), a1);
    g_cx[1][n * HW + p] = __fadd_rn(__fmul_rn(__fadd_rn(x, 0.5f), bw2), b0);
    g_cy[1][n * HW + p] = __fadd_rn(__fmul_rn(__fadd_rn(y, 0.5f), bh2), b1);
    if (p == 0) {
        float d1 = __fsqrt_rn(__fadd_rn(__fmul_rn(bw1, bw1), __fmul_rn(bh1, bh1)));
        float d2 = __fsqrt_rn(__fadd_rn(__fmul_rn(bw2, bw2), __fmul_rn(bh2, bh2)));
        g_maxdiag[n] = fmaxf(d1, d2);
    }
}

// Fused GEMM + cosine + mask + masked-mean partial reduction.
// S[p][q] = sum_c Q[c][p] * K[c][q]   (both stored [C][HW], p/q contiguous)
// Inputs rounded to TF32 to match the reference's TF32 einsum.
// 128x128 tile, BK=8, 256 threads, 8x8 per thread.
#define BM 128
#define BN 128
#define BK 8
#define TM 8
#define TN 8

__global__ __launch_bounds__(256) void gemm_loss_kernel(
    const float* __restrict__ p1, const float* __restrict__ p2,
    const float* __restrict__ z1, const float* __restrict__ z2) {

    int z = blockIdx.z;          // 0..63 : (loss, n)
    int n = z & 31;
    int which = z >> 5;          // 0 -> (p1, z2), 1 -> (p2, z1)

    const float *Q, *K, *qn, *kn, *qcx, *qcy, *kcx, *kcy;
    size_t off = (size_t)n * CDIM * HW;
    if (which == 0) {
        Q = p1 + off; K = z2 + off;
        qn = &g_norms[0][n * HW]; kn = &g_norms[3][n * HW];
        qcx = &g_cx[0][n * HW]; qcy = &g_cy[0][n * HW];
        kcx = &g_cx[1][n * HW]; kcy = &g_cy[1][n * HW];
    } else {
        Q = p2 + off; K = z1 + off;
        qn = &g_norms[1][n * HW]; kn = &g_norms[2][n * HW];
        qcx = &g_cx[1][n * HW]; qcy = &g_cy[1][n * HW];
        kcx = &g_cx[0][n * HW]; kcy = &g_cy[0][n * HW];
    }
    float maxdiag = g_maxdiag[n];

    __shared__ float As[BK][BM];
    __shared__ float Bs[BK][BN];
    __shared__ float redS[256];
    __shared__ float redC[256];

    int tid = threadIdx.x;
    int tx = tid & 15;           // 0..15 -> column group
    int ty = tid >> 4;           // 0..15 -> row group
    int pBase = blockIdx.x * BM;
    int qBase = blockIdx.y * BN;

    // global->smem load mapping: 8 k-rows x 32 float4 columns
    int lr = tid >> 5;           // 0..7
    int lc = (tid & 31) * 4;     // 0..124

    float acc[TM][TN];
#pragma unroll
    for (int i = 0; i < TM; ++i)
#pragma unroll
        for (int j = 0; j < TN; ++j) acc[i][j] = 0.f;

    for (int kt = 0; kt < CDIM; kt += BK) {
        float4 av = *(const float4*)(Q + (size_t)(kt + lr) * HW + pBase + lc);
        float4 bv = *(const float4*)(K + (size_t)(kt + lr) * HW + qBase + lc);
        // TF32-quantize operands (matches reference einsum's TF32 path)
        av.x = tf32r(av.x); av.y = tf32r(av.y); av.z = tf32r(av.z); av.w = tf32r(av.w);
        bv.x = tf32r(bv.x); bv.y = tf32r(bv.y); bv.z = tf32r(bv.z); bv.w = tf32r(bv.w);
        *(float4*)&As[lr][lc] = av;
        *(float4*)&Bs[lr][lc] = bv;
        __syncthreads();
#pragma unroll
        for (int k = 0; k < BK; ++k) {
            float a[TM], b[TN];
#pragma unroll
            for (int i = 0; i < TM; ++i) a[i] = As[k][ty * TM + i];
#pragma unroll
            for (int j = 0; j < TN; ++j) b[j] = Bs[k][tx * TN + j];
#pragma unroll
            for (int i = 0; i < TM; ++i)
#pragma unroll
                for (int j = 0; j < TN; ++j) acc[i][j] += a[i] * b[j];
        }
        __syncthreads();
    }

    // Epilogue: cosine sim + geometric mask, exactly as reference.
    float qn8[TM], qx8[TM], qy8[TM], kn8[TN], kx8[TN], ky8[TN];
#pragma unroll
    for (int i = 0; i < TM; ++i) {
        int p = pBase + ty * TM + i;
        qn8[i] = qn[p]; qx8[i] = qcx[p]; qy8[i] = qcy[p];
    }
#pragma unroll
    for (int j = 0; j < TN; ++j) {
        int q = qBase + tx * TN + j;
        kn8[j] = kn[q]; kx8[j] = kcx[q]; ky8[j] = kcy[q];
    }

    float lsum = 0.f;
    float lcnt = 0.f;
#pragma unroll
    for (int i = 0; i < TM; ++i) {
#pragma unroll
        for (int j = 0; j < TN; ++j) {
            float denom = fmaxf(__fmul_rn(qn8[i], kn8[j]), 1e-8f);
            float cosv = __fdiv_rn(acc[i][j], denom);
            // mask: separate rounding (no FMA) to match reference elementwise ops
            float dx = __fsub_rn(qx8[i], kx8[j]);
            float dy = __fsub_rn(qy8[i], ky8[j]);
            float d2 = __fadd_rn(__fmul_rn(dx, dx), __fmul_rn(dy, dy));
            float dist = __fdiv_rn(__fsqrt_rn(d2), maxdiag);
            if (dist < 16.0f) {   // pos_ratio * H = 0.5 * 32
                lsum += cosv;
                lcnt += 1.0f;
            }
        }
    }

    redS[tid] = lsum;
    redC[tid] = lcnt;
    __syncthreads();
#pragma unroll
    for (int s = 128; s > 0; s >>= 1) {
        if (tid < s) { redS[tid] += redS[tid + s]; redC[tid] += redC[tid + s]; }
        __syncthreads();
    }
    if (tid == 0) {
        atomicAdd(&g_sum[z], (double)redS[0]);
        atomicAdd(&g_cnt[z], (double)redC[0]);
    }
}

__global__ void final_kernel(float* __restrict__ out) {
    double l1 = 0.0, l2 = 0.0;
    for (int n = 0; n < 32; ++n) {
        l1 += g_sum[n]      / (g_cnt[n]      + 1e-6);
        l2 += g_sum[32 + n] / (g_cnt[32 + n] + 1e-6);
    }
    out[0] = (float)(-((l1 / 32.0) + (l2 / 32.0)) * 0.5);
}

// ---------------- launch ----------------
extern "C" void kernel_launch(void* const* d_in, const int* in_sizes, int n_in,
                              void* d_out, int out_size) {
    const float* p1 = (const float*)d_in[0];
    const float* p2 = (const float*)d_in[1];
    const float* z1 = (const float*)d_in[2];
    const float* z2 = (const float*)d_in[3];
    const float* c1 = (const float*)d_in[4];
    const float* c2 = (const float*)d_in[5];
    float* out = (float*)d_out;

    zero_kernel<<<1, 64>>>();
    norms_kernel<<<dim3(NB, 4), 1024>>>(p1, p2, z1, z2);
    centers_kernel<<<NB, 1024>>>(c1, c2);
    gemm_loss_kernel<<<dim3(8, 8, 64), 256>>>(p1, p2, z1, z2);
    final_kernel<<<1, 1>>>(out);
}

// round 5
// speedup vs baseline: 2.2179x; 2.2179x over previous
#include <cuda_runtime.h>
#include <math.h>
#include <stdint.h>

// Problem constants (fixed by reference: N=32, C=256, H=W=32)
#define NB 32
#define CDIM 256
#define HW 1024
#define WD 32

// ---------------- device scratch (no allocations allowed) ----------------
__device__ double g_sum[64];                 // masked cos sum per (loss, n)
__device__ double g_cnt[64];                 // mask count per (loss, n)
__device__ float  g_norms[4][NB * HW];       // ||.|| for p1,p2,z1,z2
__device__ float  g_cx[2][NB * HW];          // centers x for coord_1, coord_2
__device__ float  g_cy[2][NB * HW];          // centers y
__device__ float  g_maxdiag[NB];             // max(diag1, diag2) per n

// Round fp32 -> TF32 (10-bit mantissa), same conversion cuBLAS/CUTLASS use.
__device__ __forceinline__ float tf32r(float x) {
    uint32_t u;
    asm("cvt.rna.tf32.f32 %0, %1;" : "=r"(u) : "f"(x));
    return __uint_as_float(u);
}

// m16n8k8 TF32 MMA, fp32 accumulate (matches reference's TF32 einsum path)
__device__ __forceinline__ void mma_tf32(float* d, const float* a, const float* b) {
    asm volatile(
        "mma.sync.aligned.m16n8k8.row.col.f32.tf32.tf32.f32 "
        "{%0,%1,%2,%3}, {%4,%5,%6,%7}, {%8,%9}, {%0,%1,%2,%3};\n"
        : "+f"(d[0]), "+f"(d[1]), "+f"(d[2]), "+f"(d[3])
        : "r"(__float_as_uint(a[0])), "r"(__float_as_uint(a[1])),
          "r"(__float_as_uint(a[2])), "r"(__float_as_uint(a[3])),
          "r"(__float_as_uint(b[0])), "r"(__float_as_uint(b[1])));
}

// ---------------- kernels ----------------
__global__ void zero_kernel() {
    int i = threadIdx.x;
    if (i < 64) { g_sum[i] = 0.0; g_cnt[i] = 0.0; }
}

// grid (NB, 4), block 1024: tensor t, sample n, one thread per spatial p.
__global__ void norms_kernel(const float* __restrict__ p1, const float* __restrict__ p2,
                             const float* __restrict__ z1, const float* __restrict__ z2) {
    int n = blockIdx.x;
    int t = blockIdx.y;
    int p = threadIdx.x;
    const float* src = (t == 0) ? p1 : (t == 1) ? p2 : (t == 2) ? z1 : z2;
    const float* base = src + (size_t)n * CDIM * HW + p;
    float acc = 0.f;
#pragma unroll 8
    for (int c = 0; c < CDIM; ++c) {
        float v = base[(size_t)c * HW];
        acc += v * v;
    }
    g_norms[t][n * HW + p] = sqrtf(acc);
}

// grid (NB), block 1024: centers + max_diag, exact reference arithmetic.
__global__ void centers_kernel(const float* __restrict__ c1, const float* __restrict__ c2) {
    int n = blockIdx.x;
    int p = threadIdx.x;
    float a0 = c1[n * 4 + 0], a1 = c1[n * 4 + 1], a2 = c1[n * 4 + 2], a3 = c1[n * 4 + 3];
    float b0 = c2[n * 4 + 0], b1 = c2[n * 4 + 1], b2 = c2[n * 4 + 2], b3 = c2[n * 4 + 3];
    float bw1 = __fdiv_rn(__fsub_rn(a2, a0), 32.0f), bh1 = __fdiv_rn(__fsub_rn(a3, a1), 32.0f);
    float bw2 = __fdiv_rn(__fsub_rn(b2, b0), 32.0f), bh2 = __fdiv_rn(__fsub_rn(b3, b1), 32.0f);
    float x = (float)(p % WD);
    float y = (float)(p / WD);
    g_cx[0][n * HW + p] = __fadd_rn(__fmul_rn(__fadd_rn(x, 0.5f), bw1), a0);
    g_cy[0][n * HW + p] = __fadd_rn(__fmul_rn(__fadd_rn(y, 0.5f), bh1), a1);
    g_cx[1][n * HW + p] = __fadd_rn(__fmul_rn(__fadd_rn(x, 0.5f), bw2), b0);
    g_cy[1][n * HW + p] = __fadd_rn(__fmul_rn(__fadd_rn(y, 0.5f), bh2), b1);
    if (p == 0) {
        float d1 = __fsqrt_rn(__fadd_rn(__fmul_rn(bw1, bw1), __fmul_rn(bh1, bh1)));
        float d2 = __fsqrt_rn(__fadd_rn(__fmul_rn(bw2, bw2), __fmul_rn(bh2, bh2)));
        g_maxdiag[n] = fmaxf(d1, d2);
    }
}

// Fused TF32 tensor-core GEMM + cosine + mask + masked-mean reduction.
// S[p][q] = sum_c Q[c][p] * K[c][q]  (A = Q^T row-major, B = K col-major-as-[k][n])
// 128x128 tile, BK=16 double-buffered, 256 threads = 8 warps (2x4),
// each warp 64x32 via 4x4 m16n8k8 fragments.
#define BM 128
#define BN 128
#define BK 16
#define LDS_ 132   // +4 padding: fragment loads hit distinct banks

__global__ __launch_bounds__(256) void gemm_loss_kernel(
    const float* __restrict__ p1, const float* __restrict__ p2,
    const float* __restrict__ z1, const float* __restrict__ z2) {

    int z = blockIdx.z;          // 0..63 : (loss, n)
    int n = z & 31;
    int which = z >> 5;          // 0 -> (p1, z2), 1 -> (p2, z1)

    const float *Q, *K, *qn, *kn, *qcx, *qcy, *kcx, *kcy;
    size_t off = (size_t)n * CDIM * HW;
    if (which == 0) {
        Q = p1 + off; K = z2 + off;
        qn = &g_norms[0][n * HW]; kn = &g_norms[3][n * HW];
        qcx = &g_cx[0][n * HW]; qcy = &g_cy[0][n * HW];
        kcx = &g_cx[1][n * HW]; kcy = &g_cy[1][n * HW];
    } else {
        Q = p2 + off; K = z1 + off;
        qn = &g_norms[1][n * HW]; kn = &g_norms[2][n * HW];
        qcx = &g_cx[1][n * HW]; qcy = &g_cy[1][n * HW];
        kcx = &g_cx[0][n * HW]; kcy = &g_cy[0][n * HW];
    }
    float maxdiag = g_maxdiag[n];

    __shared__ float As[2][BK][LDS_];
    __shared__ float Bs[2][BK][LDS_];
    __shared__ float redS[256];
    __shared__ float redC[256];

    int tid  = threadIdx.x;
    int lane = tid & 31;
    int warp = tid >> 5;          // 0..7
    int gid  = lane >> 2;         // 0..7 (groupID)
    int tig  = lane & 3;          // 0..3 (thread-in-group)
    int warpM = warp >> 2;        // 0..1 -> 64-row band
    int warpN = warp & 3;         // 0..3 -> 32-col band
    int pBase = blockIdx.x * BM;
    int qBase = blockIdx.y * BN;

    // global->smem mapping: thread loads rows lr and lr+8, 4 floats at lc
    int lr = tid >> 5;            // 0..7
    int lc = (tid & 31) * 4;      // 0..124

    float d[4][4][4];
#pragma unroll
    for (int mt = 0; mt < 4; ++mt)
#pragma unroll
        for (int nt = 0; nt < 4; ++nt)
#pragma unroll
            for (int r = 0; r < 4; ++r) d[mt][nt][r] = 0.f;

    float4 pa0, pa1, pb0, pb1;

    // prefetch tile 0
    {
        const float* qr = Q + (size_t)lr * HW + pBase + lc;
        pa0 = *(const float4*)qr;
        pa1 = *(const float4*)(qr + (size_t)8 * HW);
        const float* kr = K + (size_t)lr * HW + qBase + lc;
        pb0 = *(const float4*)kr;
        pb1 = *(const float4*)(kr + (size_t)8 * HW);
    }
    // store (TF32-rounded) to buffer 0
    {
        float* a0 = &As[0][lr][lc];     float* a1 = &As[0][lr + 8][lc];
        float* b0 = &Bs[0][lr][lc];     float* b1 = &Bs[0][lr + 8][lc];
        a0[0]=tf32r(pa0.x); a0[1]=tf32r(pa0.y); a0[2]=tf32r(pa0.z); a0[3]=tf32r(pa0.w);
        a1[0]=tf32r(pa1.x); a1[1]=tf32r(pa1.y); a1[2]=tf32r(pa1.z); a1[3]=tf32r(pa1.w);
        b0[0]=tf32r(pb0.x); b0[1]=tf32r(pb0.y); b0[2]=tf32r(pb0.z); b0[3]=tf32r(pb0.w);
        b1[0]=tf32r(pb1.x); b1[1]=tf32r(pb1.y); b1[2]=tf32r(pb1.z); b1[3]=tf32r(pb1.w);
    }
    __syncthreads();

#pragma unroll 1
    for (int kt = 0; kt < CDIM / BK; ++kt) {
        int cur = kt & 1;
        if (kt < CDIM / BK - 1) {
            const float* qr = Q + (size_t)((kt + 1) * BK + lr) * HW + pBase + lc;
            pa0 = *(const float4*)qr;
            pa1 = *(const float4*)(qr + (size_t)8 * HW);
            const float* kr = K + (size_t)((kt + 1) * BK + lr) * HW + qBase + lc;
            pb0 = *(const float4*)kr;
            pb1 = *(const float4*)(kr + (size_t)8 * HW);
        }
        // compute: two k8 steps on buffer cur
#pragma unroll
        for (int kk = 0; kk < 2; ++kk) {
            int c0 = kk * 8;
            float af[4][4], bf[4][2];
#pragma unroll
            for (int mt = 0; mt < 4; ++mt) {
                int pm = warpM * 64 + mt * 16 + gid;
                af[mt][0] = As[cur][c0 + tig][pm];
                af[mt][1] = As[cur][c0 + tig][pm + 8];
                af[mt][2] = As[cur][c0 + tig + 4][pm];
                af[mt][3] = As[cur][c0 + tig + 4][pm + 8];
            }
#pragma unroll
            for (int nt = 0; nt < 4; ++nt) {
                int qm = warpN * 32 + nt * 8 + gid;
                bf[nt][0] = Bs[cur][c0 + tig][qm];
                bf[nt][1] = Bs[cur][c0 + tig + 4][qm];
            }
#pragma unroll
            for (int mt = 0; mt < 4; ++mt)
#pragma unroll
                for (int nt = 0; nt < 4; ++nt)
                    mma_tf32(d[mt][nt], af[mt], bf[nt]);
        }
        if (kt < CDIM / BK - 1) {
            int nxt = cur ^ 1;
            float* a0 = &As[nxt][lr][lc];     float* a1 = &As[nxt][lr + 8][lc];
            float* b0 = &Bs[nxt][lr][lc];     float* b1 = &Bs[nxt][lr + 8][lc];
            a0[0]=tf32r(pa0.x); a0[1]=tf32r(pa0.y); a0[2]=tf32r(pa0.z); a0[3]=tf32r(pa0.w);
            a1[0]=tf32r(pa1.x); a1[1]=tf32r(pa1.y); a1[2]=tf32r(pa1.z); a1[3]=tf32r(pa1.w);
            b0[0]=tf32r(pb0.x); b0[1]=tf32r(pb0.y); b0[2]=tf32r(pb0.z); b0[3]=tf32r(pb0.w);
            b1[0]=tf32r(pb1.x); b1[1]=tf32r(pb1.y); b1[2]=tf32r(pb1.z); b1[3]=tf32r(pb1.w);
            __syncthreads();
        }
    }

    // Epilogue: cosine sim + geometric mask on MMA D-fragment layout.
    // d[mt][nt][r]: r0=(p0,q0) r1=(p0,q0+1) r2=(p0+8,q0) r3=(p0+8,q0+1)
    //   p0 = pBase + warpM*64 + mt*16 + gid, q0 = qBase + warpN*32 + nt*8 + 2*tig
    float qnv[4][2], qxv[4][2], qyv[4][2];
#pragma unroll
    for (int mt = 0; mt < 4; ++mt)
#pragma unroll
        for (int i2 = 0; i2 < 2; ++i2) {
            int p = pBase + warpM * 64 + mt * 16 + gid + i2 * 8;
            qnv[mt][i2] = qn[p]; qxv[mt][i2] = qcx[p]; qyv[mt][i2] = qcy[p];
        }
    float knv[4][2], kxv[4][2], kyv[4][2];
#pragma unroll
    for (int nt = 0; nt < 4; ++nt)
#pragma unroll
        for (int j2 = 0; j2 < 2; ++j2) {
            int q = qBase + warpN * 32 + nt * 8 + 2 * tig + j2;
            knv[nt][j2] = kn[q]; kxv[nt][j2] = kcx[q]; kyv[nt][j2] = kcy[q];
        }

    float lsum = 0.f, lcnt = 0.f;
#pragma unroll
    for (int mt = 0; mt < 4; ++mt) {
#pragma unroll
        for (int nt = 0; nt < 4; ++nt) {
#pragma unroll
            for (int r = 0; r < 4; ++r) {
                int i2 = r >> 1, j2 = r & 1;
                float denom = fmaxf(__fmul_rn(qnv[mt][i2], knv[nt][j2]), 1e-8f);
                float cosv = __fdiv_rn(d[mt][nt][r], denom);
                float dx = __fsub_rn(qxv[mt][i2], kxv[nt][j2]);
                float dy = __fsub_rn(qyv[mt][i2], kyv[nt][j2]);
                float d2v = __fadd_rn(__fmul_rn(dx, dx), __fmul_rn(dy, dy));
                float dist = __fdiv_rn(__fsqrt_rn(d2v), maxdiag);
                if (dist < 16.0f) {   // pos_ratio * H = 0.5 * 32
                    lsum += cosv;
                    lcnt += 1.0f;
                }
            }
        }
    }

    redS[tid] = lsum;
    redC[tid] = lcnt;
    __syncthreads();
#pragma unroll
    for (int s = 128; s > 0; s >>= 1) {
        if (tid < s) { redS[tid] += redS[tid + s]; redC[tid] += redC[tid + s]; }
        __syncthreads();
    }
    if (tid == 0) {
        atomicAdd(&g_sum[z], (double)redS[0]);
        atomicAdd(&g_cnt[z], (double)redC[0]);
    }
}

__global__ void final_kernel(float* __restrict__ out) {
    double l1 = 0.0, l2 = 0.0;
    for (int n = 0; n < 32; ++n) {
        l1 += g_sum[n]      / (g_cnt[n]      + 1e-6);
        l2 += g_sum[32 + n] / (g_cnt[32 + n] + 1e-6);
    }
    out[0] = (float)(-((l1 / 32.0) + (l2 / 32.0)) * 0.5);
}

// ---------------- launch ----------------
extern "C" void kernel_launch(void* const* d_in, const int* in_sizes, int n_in,
                              void* d_out, int out_size) {
    const float* p1 = (const float*)d_in[0];
    const float* p2 = (const float*)d_in[1];
    const float* z1 = (const float*)d_in[2];
    const float* z2 = (const float*)d_in[3];
    const float* c1 = (const float*)d_in[4];
    const float* c2 = (const float*)d_in[5];
    float* out = (float*)d_out;

    zero_kernel<<<1, 64>>>();
    norms_kernel<<<dim3(NB, 4), 1024>>>(p1, p2, z1, z2);
    centers_kernel<<<NB, 1024>>>(c1, c2);
    gemm_loss_kernel<<<dim3(8, 8, 64), 256>>>(p1, p2, z1, z2);
    final_kernel<<<1, 1>>>(out);
}